// round 5
// baseline (speedup 1.0000x reference)
#include <cuda_runtime.h>
#include <cuda_bf16.h>
#include <math.h>

// HashedInterpolator: 3-D hash-grid trilinear interpolation.
// position: [B,3] f32 in [0,1);  hash_table: [524288,4] f32;  out: [B,4] f32.
//
// R5: lane-pair x-merge + 2 points/thread (MLP=8 gathers/lane) with register
// dieting so occupancy stays high: indices computed first, all 8 gathers
// issued, THEN weights recomputed from smem while loads are in flight.
// __launch_bounds__(256,5) caps regs at ~51 -> ~40 warps/SM.

#define HG_ENTRIES 524288
#define HG_MASK    (HG_ENTRIES - 1)
#define HG_P1      19349663u
#define HG_P2      83492791u

#define TPB   256
#define HALF  (TPB / 2)        // 128 lane-pairs per block
#define PPB   (TPB)            // 256 points per block (2 per lane pair)

__global__ __launch_bounds__(TPB, 5) void hashed_interp_kernel(
    const float* __restrict__ pos,
    const float4* __restrict__ table,
    float4* __restrict__ out,
    int batch)
{
    __shared__ float sp[3 * PPB];

    int t = threadIdx.x;
    int base = blockIdx.x * PPB;

    // Stage this block's positions (192 float4s) coalesced.
    {
        int nfloats = 3 * (batch - base);
        if (nfloats > 3 * PPB) nfloats = 3 * PPB;
        const float4* src = (const float4*)(pos + 3 * base);  // 3072B-aligned
        int nvec = nfloats >> 2;
        if (t < nvec) ((float4*)sp)[t] = src[t];
        int rem = nfloats & 3;
        if (t < rem) sp[(nvec << 2) + t] = pos[3 * base + (nvec << 2) + t];
    }
    __syncthreads();

    int slot = t >> 1;          // 0..127
    int xbit = t & 1;
    int iA = base + slot;
    int iB = base + slot + HALF;
    // batch = 2^21 divides PPB exactly in this problem; guard is uniform.
    bool full = (base + PPB) <= batch;
    bool hasA = full || (iA < batch);
    bool hasB = full || (iB < batch);

    // ---- indices only (minimal live state), then issue all 8 gathers ----
    unsigned a00=0,a01=0,a10=0,a11=0, b00=0,b01=0,b10=0,b11=0;
    {
        float px = sp[3 * slot + 0];
        float py = sp[3 * slot + 1];
        float pz = sp[3 * slot + 2];
        unsigned hx  = (unsigned)((int)floorf(px * 512.0f) + xbit);
        int ly = (int)floorf(py * 512.0f);
        int lz = (int)floorf(pz * 512.0f);
        unsigned hy0 = (unsigned)ly * HG_P1;
        unsigned hy1 = hy0 + HG_P1;
        unsigned hz0 = (unsigned)lz * HG_P2;
        unsigned hz1 = hz0 + HG_P2;
        a00 = (hx ^ hy0 ^ hz0) & HG_MASK;
        a01 = (hx ^ hy0 ^ hz1) & HG_MASK;
        a10 = (hx ^ hy1 ^ hz0) & HG_MASK;
        a11 = (hx ^ hy1 ^ hz1) & HG_MASK;
    }
    {
        int s2 = slot + HALF;
        float px = sp[3 * s2 + 0];
        float py = sp[3 * s2 + 1];
        float pz = sp[3 * s2 + 2];
        unsigned hx  = (unsigned)((int)floorf(px * 512.0f) + xbit);
        int ly = (int)floorf(py * 512.0f);
        int lz = (int)floorf(pz * 512.0f);
        unsigned hy0 = (unsigned)ly * HG_P1;
        unsigned hy1 = hy0 + HG_P1;
        unsigned hz0 = (unsigned)lz * HG_P2;
        unsigned hz1 = hz0 + HG_P2;
        b00 = (hx ^ hy0 ^ hz0) & HG_MASK;
        b01 = (hx ^ hy0 ^ hz1) & HG_MASK;
        b10 = (hx ^ hy1 ^ hz0) & HG_MASK;
        b11 = (hx ^ hy1 ^ hz1) & HG_MASK;
    }

    float4 vA00, vA01, vA10, vA11, vB00, vB01, vB10, vB11;
    if (hasA) {
        vA00 = __ldcg(&table[a00]);
        vA01 = __ldcg(&table[a01]);
        vA10 = __ldcg(&table[a10]);
        vA11 = __ldcg(&table[a11]);
    }
    if (hasB) {
        vB00 = __ldcg(&table[b00]);
        vB01 = __ldcg(&table[b01]);
        vB10 = __ldcg(&table[b10]);
        vB11 = __ldcg(&table[b11]);
    }

    const float inv = 1.0f / 512.0f;   // exact; /size == *512 exactly

    // ---- point A: recompute weights from smem while loads are in flight ----
    if (hasA) {
        float px = sp[3 * slot + 0];
        float py = sp[3 * slot + 1];
        float pz = sp[3 * slot + 2];
        int lx = (int)floorf(px * 512.0f);
        int ly = (int)floorf(py * 512.0f);
        int lz = (int)floorf(pz * 512.0f);
        float wx0 = (px - (float)lx * inv) * 512.0f;
        float wx1 = ((float)(lx + 1) * inv - px) * 512.0f;
        float wy0 = (py - (float)ly * inv) * 512.0f;
        float wy1 = ((float)(ly + 1) * inv - py) * 512.0f;
        float wz0 = (pz - (float)lz * inv) * 512.0f;
        float wz1 = ((float)(lz + 1) * inv - pz) * 512.0f;
        float wx = xbit ? wx1 : wx0;

        float w00 = wx * wy0 * wz0;
        float w01 = wx * wy0 * wz1;
        float w10 = wx * wy1 * wz0;
        float w11 = wx * wy1 * wz1;

        float4 acc;
        acc.x = vA00.x * w00;  acc.y = vA00.y * w00;
        acc.z = vA00.z * w00;  acc.w = vA00.w * w00;
        acc.x = fmaf(vA01.x, w01, acc.x);  acc.y = fmaf(vA01.y, w01, acc.y);
        acc.z = fmaf(vA01.z, w01, acc.z);  acc.w = fmaf(vA01.w, w01, acc.w);
        acc.x = fmaf(vA10.x, w10, acc.x);  acc.y = fmaf(vA10.y, w10, acc.y);
        acc.z = fmaf(vA10.z, w10, acc.z);  acc.w = fmaf(vA10.w, w10, acc.w);
        acc.x = fmaf(vA11.x, w11, acc.x);  acc.y = fmaf(vA11.y, w11, acc.y);
        acc.z = fmaf(vA11.z, w11, acc.z);  acc.w = fmaf(vA11.w, w11, acc.w);

        acc.x += __shfl_xor_sync(0xffffffffu, acc.x, 1);
        acc.y += __shfl_xor_sync(0xffffffffu, acc.y, 1);
        acc.z += __shfl_xor_sync(0xffffffffu, acc.z, 1);
        acc.w += __shfl_xor_sync(0xffffffffu, acc.w, 1);
        if (xbit == 0) __stcs(&out[iA], acc);
    }

    // ---- point B ----
    if (hasB) {
        int s2 = slot + HALF;
        float px = sp[3 * s2 + 0];
        float py = sp[3 * s2 + 1];
        float pz = sp[3 * s2 + 2];
        int lx = (int)floorf(px * 512.0f);
        int ly = (int)floorf(py * 512.0f);
        int lz = (int)floorf(pz * 512.0f);
        float wx0 = (px - (float)lx * inv) * 512.0f;
        float wx1 = ((float)(lx + 1) * inv - px) * 512.0f;
        float wy0 = (py - (float)ly * inv) * 512.0f;
        float wy1 = ((float)(ly + 1) * inv - py) * 512.0f;
        float wz0 = (pz - (float)lz * inv) * 512.0f;
        float wz1 = ((float)(lz + 1) * inv - pz) * 512.0f;
        float wx = xbit ? wx1 : wx0;

        float w00 = wx * wy0 * wz0;
        float w01 = wx * wy0 * wz1;
        float w10 = wx * wy1 * wz0;
        float w11 = wx * wy1 * wz1;

        float4 acc;
        acc.x = vB00.x * w00;  acc.y = vB00.y * w00;
        acc.z = vB00.z * w00;  acc.w = vB00.w * w00;
        acc.x = fmaf(vB01.x, w01, acc.x);  acc.y = fmaf(vB01.y, w01, acc.y);
        acc.z = fmaf(vB01.z, w01, acc.z);  acc.w = fmaf(vB01.w, w01, acc.w);
        acc.x = fmaf(vB10.x, w10, acc.x);  acc.y = fmaf(vB10.y, w10, acc.y);
        acc.z = fmaf(vB10.z, w10, acc.z);  acc.w = fmaf(vB10.w, w10, acc.w);
        acc.x = fmaf(vB11.x, w11, acc.x);  acc.y = fmaf(vB11.y, w11, acc.y);
        acc.z = fmaf(vB11.z, w11, acc.z);  acc.w = fmaf(vB11.w, w11, acc.w);

        acc.x += __shfl_xor_sync(0xffffffffu, acc.x, 1);
        acc.y += __shfl_xor_sync(0xffffffffu, acc.y, 1);
        acc.z += __shfl_xor_sync(0xffffffffu, acc.z, 1);
        acc.w += __shfl_xor_sync(0xffffffffu, acc.w, 1);
        if (xbit == 0) __stcs(&out[iB], acc);
    }
}

extern "C" void kernel_launch(void* const* d_in, const int* in_sizes, int n_in,
                              void* d_out, int out_size)
{
    const float* pos = (const float*)d_in[0];
    const float4* table = (const float4*)d_in[1];
    float4* out = (float4*)d_out;
    int batch = in_sizes[0] / 3;

    int blocks = (batch + PPB - 1) / PPB;
    hashed_interp_kernel<<<blocks, TPB>>>(pos, table, out, batch);
}